// round 4
// baseline (speedup 1.0000x reference)
#include <cuda_runtime.h>
#include <cstddef>

#define Bc 16
#define Fc 4
#define Kc 16
#define KH 8          // k's per block (k-half)
#define Yc 16
#define Xc 16
#define Pc 16
#define Tc 8
#define NT 1024

typedef unsigned long long u64;

// sm_103a packed f32x2 ops (PTX-only; ptxas never auto-fuses these)
__device__ __forceinline__ u64 pk2(float lo, float hi) {
    u64 r; asm("mov.b64 %0, {%1,%2};" : "=l"(r) : "f"(lo), "f"(hi)); return r;
}
__device__ __forceinline__ void unpk2(u64 v, float& lo, float& hi) {
    asm("mov.b64 {%0,%1}, %2;" : "=f"(lo), "=f"(hi) : "l"(v));
}
__device__ __forceinline__ u64 fma2_(u64 a, u64 b, u64 c) {
    u64 d; asm("fma.rn.f32x2 %0, %1, %2, %3;" : "=l"(d) : "l"(a), "l"(b), "l"(c)); return d;
}
__device__ __forceinline__ u64 mul2_(u64 a, u64 b) {
    u64 d; asm("mul.rn.f32x2 %0, %1, %2;" : "=l"(d) : "l"(a), "l"(b)); return d;
}

// One block = (b, f, k-half). 1024 threads: thread = (yh:2b, x:4b, p:4b),
// each thread contracts 4 y-rows of 8 t-values for 8 k's.
// Time contraction: Horner in r^2 on (even,odd)-packed f32x2 lanes; the
// odd-lane r-correction is deferred to after the y-loop (accumulate (E,O)).
__global__ void __launch_bounds__(NT, 1) pkl_fused(
    const float* __restrict__ field, const float* __restrict__ darea,
    const float* __restrict__ dlev,  const float* __restrict__ dtime,
    const float* __restrict__ lat_mean, const float* __restrict__ lat_logstd,
    const float* __restrict__ lon_mean, const float* __restrict__ lon_logstd,
    const float* __restrict__ lev_mean, const float* __restrict__ lev_logstd,
    const float* __restrict__ time_logtau, float* __restrict__ out)
{
    int blk = blockIdx.x;
    int kh = blk & 1;
    int f  = (blk >> 1) & 3;
    int b  = blk >> 3;
    int tid  = threadIdx.x;
    int lane = tid & 31;
    int warp = tid >> 5;

    // ---- issue the first field loads immediately (independent of setup) ----
    int p  = tid & 15;
    int x  = (tid >> 4) & 15;
    int yh = tid >> 8;                     // 0..3
    const ulonglong2* src = (const ulonglong2*)(field
        + (size_t)(b * Fc + f) * (Yc * Xc * Pc * Tc)
        + ((yh * 4) * Xc * Pc + x * Pc + p) * Tc);
    ulonglong2 v0 = src[0], v1 = src[1];   // row = 8 floats = 2x ulonglong2
    // y-stride = X*P*T = 2048 floats = 512 ulonglong2

    __shared__ __align__(16) float sklat[Yc][KH];
    __shared__ __align__(16) float sklon[Xc][KH];
    __shared__ __align__(16) float sklev[Pc][KH];
    __shared__ float srate[KH], sr2[KH], swinv[KH];
    __shared__ float sdamean[Yc * Xc], sda[Yc * Xc];
    __shared__ float sdlmean[Pc], sdl[Pc], sdtm[Tc], sdt[Tc];
    __shared__ float sred[32][KH];

    // ---- 1D parametric kernels for this block's 8 k's (384 gaussians) ----
    if (tid < 3 * 16 * KH) {
        int j   = tid & 7;
        int d   = (tid >> 3) & 15;
        int dim = tid >> 7;
        int fk  = f * Kc + kh * KH + j;
        float coord = -1.0f + 2.0f * (float)d / 15.0f;
        float m, ls;
        if (dim == 0)      { m = lat_mean[fk]; ls = lat_logstd[fk]; }
        else if (dim == 1) { m = lon_mean[fk]; ls = lon_logstd[fk]; }
        else               { m = lev_mean[fk]; ls = lev_logstd[fk]; }
        float z = (coord - m) * expf(-ls);
        float g = expf(-0.5f * z * z);
        if (dim == 0)      sklat[d][j] = g;
        else if (dim == 1) sklon[d][j] = g;
        else               sklev[d][j] = g;
    }
    if (tid >= 512 && tid < 512 + KH) {
        int j = tid - 512;
        int fk = f * Kc + kh * KH + j;
        float tau = expf(time_logtau[fk]) + 1e-4f;
        float r = expf(-1.0f / tau);       // ktime[t] = r^t
        srate[j] = r;
        sr2[j] = r * r;
    }
    // ---- batch means + this sample's quadrature weights ----
    if (tid >= 768) {
        int i = tid - 768;
        float s = 0.f;
        #pragma unroll
        for (int bb = 0; bb < Bc; bb++) s += darea[bb * 256 + i];
        sdamean[i] = s * (1.f / 16.f);
        sda[i] = darea[b * 256 + i];
    }
    if (tid >= 704 && tid < 704 + Pc) {
        int i = tid - 704;
        float s = 0.f;
        #pragma unroll
        for (int bb = 0; bb < Bc; bb++) s += dlev[bb * Pc + i];
        sdlmean[i] = s * (1.f / 16.f);
        sdl[i] = dlev[b * Pc + i];
    }
    if (tid >= 736 && tid < 736 + Tc) {
        int i = tid - 736;
        float s = 0.f;
        #pragma unroll
        for (int bb = 0; bb < Bc; bb++) s += dtime[bb * Tc + i];
        sdtm[i] = s * (1.f / 16.f);
        sdt[i] = dtime[b * Tc + i];
    }
    __syncthreads();

    // ---- separable normalization integral -> 1/(I + eps) ----
    {
        float c[KH];
        #pragma unroll
        for (int j = 0; j < KH; j++) c[j] = 0.f;
        if (tid < 256) {
            int yi = tid >> 4, xi = tid & 15;
            float dm = sdamean[tid];
            #pragma unroll
            for (int j = 0; j < KH; j++) c[j] = dm * sklat[yi][j] * sklon[xi][j];
        }
        if (warp < 8) {
            #pragma unroll
            for (int j = 0; j < KH; j++) {
                float v = c[j];
                #pragma unroll
                for (int o = 16; o > 0; o >>= 1) v += __shfl_xor_sync(0xFFFFFFFFu, v, o);
                if (lane == 0) sred[warp][j] = v;
            }
        }
        __syncthreads();
        if (tid < KH) {
            float Syx = 0.f;
            #pragma unroll
            for (int w = 0; w < 8; w++) Syx += sred[w][tid];
            float Sp = 0.f;
            #pragma unroll
            for (int pp = 0; pp < Pc; pp++) Sp = fmaf(sklev[pp][tid], sdlmean[pp], Sp);
            float r = srate[tid];
            float St = sdtm[Tc - 1];
            #pragma unroll
            for (int t = Tc - 2; t >= 0; t--) St = fmaf(St, r, sdtm[t]);
            swinv[tid] = 1.0f / (Syx * Sp * St + 1e-4f);
        }
        __syncthreads();   // sred reused below; swinv must be visible
    }

    // ---- main contraction ----
    u64 dt2[4];
    #pragma unroll
    for (int i = 0; i < 4; i++) dt2[i] = pk2(sdt[2 * i], sdt[2 * i + 1]);
    u64 s2[KH];
    #pragma unroll
    for (int k = 0; k < KH; k++) s2[k] = pk2(sr2[k], sr2[k]);
    u64 acc2[KH];
    #pragma unroll
    for (int k = 0; k < KH; k++) acc2[k] = pk2(0.f, 0.f);

    #pragma unroll
    for (int yy = 0; yy < 4; yy++) {
        int y = yh * 4 + yy;
        float dav = sda[y * 16 + x];
        u64 dada = pk2(dav, dav);
        // q_i = f-pair * (dt-pair * darea); (even,odd) t-lanes stay packed
        u64 q0 = mul2_(v0.x, mul2_(dt2[0], dada));
        u64 q1 = mul2_(v0.y, mul2_(dt2[1], dada));
        u64 q2 = mul2_(v1.x, mul2_(dt2[2], dada));
        u64 q3 = mul2_(v1.y, mul2_(dt2[3], dada));
        if (yy < 3) { v0 = src[(yy + 1) * 512]; v1 = src[(yy + 1) * 512 + 1]; }
        #pragma unroll
        for (int k = 0; k < KH; k++) {
            float wk = sklat[y][k];            // LDS broadcast (uniform in warp)
            u64 wk2 = pk2(wk, wk);
            u64 d = fma2_(q3, s2[k], q2);      // Horner in r^2, lanes (E,O)
            d = fma2_(d, s2[k], q1);
            d = fma2_(d, s2[k], q0);
            acc2[k] = fma2_(wk2, d, acc2[k]);  // (Sum wk*E, Sum wk*O)
        }
    }

    // deferred odd-lane correction + (x,p)-dependent factors, once per k
    float dlp = sdl[p];
    float av[KH];
    #pragma unroll
    for (int k = 0; k < KH; k++) {
        float E, O;
        unpk2(acc2[k], E, O);
        float dot = fmaf(srate[k], O, E);
        av[k] = dot * (sklon[x][k] * sklev[p][k] * dlp);
    }

    // ---- deterministic block reduction: shfl + fixed-order shared sum ----
    #pragma unroll
    for (int j = 0; j < KH; j++) {
        float v = av[j];
        #pragma unroll
        for (int o = 16; o > 0; o >>= 1) v += __shfl_xor_sync(0xFFFFFFFFu, v, o);
        if (lane == 0) sred[warp][j] = v;
    }
    __syncthreads();
    if (tid < KH) {
        float s = 0.f;
        #pragma unroll
        for (int w = 0; w < 32; w++) s += sred[w][tid];
        out[b * (Fc * Kc) + f * Kc + kh * KH + tid] = s * swinv[tid];
    }
}

extern "C" void kernel_launch(void* const* d_in, const int* in_sizes, int n_in,
                              void* d_out, int out_size)
{
    pkl_fused<<<Bc * Fc * 2, NT>>>(
        (const float*)d_in[0], (const float*)d_in[1],
        (const float*)d_in[2], (const float*)d_in[3],
        (const float*)d_in[4], (const float*)d_in[5],
        (const float*)d_in[6], (const float*)d_in[7],
        (const float*)d_in[8], (const float*)d_in[9],
        (const float*)d_in[10], (float*)d_out);
}

// round 5
// speedup vs baseline: 1.4226x; 1.4226x over previous
#include <cuda_runtime.h>
#include <cstddef>

#define Bc 16
#define Fc 4
#define Kc 16
#define KH 8          // k's per block (k-half)
#define Yc 16
#define Xc 16
#define Pc 16
#define Tc 8
#define NT 1024

typedef unsigned long long u64;

// sm_103a packed f32x2 ops (PTX-only; ptxas never auto-fuses these)
__device__ __forceinline__ u64 pk2(float lo, float hi) {
    u64 r; asm("mov.b64 %0, {%1,%2};" : "=l"(r) : "f"(lo), "f"(hi)); return r;
}
__device__ __forceinline__ void unpk2(u64 v, float& lo, float& hi) {
    asm("mov.b64 {%0,%1}, %2;" : "=f"(lo), "=f"(hi) : "l"(v));
}
__device__ __forceinline__ u64 fma2_(u64 a, u64 b, u64 c) {
    u64 d; asm("fma.rn.f32x2 %0, %1, %2, %3;" : "=l"(d) : "l"(a), "l"(b), "l"(c)); return d;
}
__device__ __forceinline__ u64 mul2_(u64 a, u64 b) {
    u64 d; asm("mul.rn.f32x2 %0, %1, %2;" : "=l"(d) : "l"(a), "l"(b)); return d;
}

// One block = (b, f, k-half). 1024 threads: thread = (yh:2b, x:4b, p:4b),
// 4 y-rows of 8 t-values for 8 k's.
// Row math: q_i = f-pair * (dt*darea)-pair  [4 LDS.64 + 4 mul2, no MOVs],
// Horner in r^2 over (even,odd) packed lanes, odd-lane r-correction deferred
// to after the whole y-loop. All warp-uniform constants are pre-duplicated
// u64 pairs in SMEM -> zero register cost, LDS broadcasts only.
__global__ void __launch_bounds__(NT, 1) pkl_fused(
    const float* __restrict__ field, const float* __restrict__ darea,
    const float* __restrict__ dlev,  const float* __restrict__ dtime,
    const float* __restrict__ lat_mean, const float* __restrict__ lat_logstd,
    const float* __restrict__ lon_mean, const float* __restrict__ lon_logstd,
    const float* __restrict__ lev_mean, const float* __restrict__ lev_logstd,
    const float* __restrict__ time_logtau, float* __restrict__ out)
{
    int blk = blockIdx.x;
    int kh = blk & 1;
    int f  = (blk >> 1) & 3;
    int b  = blk >> 3;
    int tid  = threadIdx.x;
    int lane = tid & 31;
    int warp = tid >> 5;

    __shared__ __align__(16) float sklat[Yc][KH];
    __shared__ __align__(16) float sklon[Xc][KH];
    __shared__ __align__(16) float sklev[Pc][KH];
    __shared__ __align__(16) u64 sklat2[Yc][KH];    // (klat, klat)
    __shared__ __align__(16) u64 ss2[KH];           // (r^2, r^2)
    __shared__ __align__(16) u64 sdtda[Yc * Xc * 4];// (dt[2i]*da, dt[2i+1]*da)
    __shared__ float srate[KH], sr2[KH], swinv[KH];
    __shared__ float sdamean[Yc * Xc], sda[Yc * Xc];
    __shared__ float sdlmean[Pc], sdl[Pc], sdtm[Tc], sdt[Tc];
    __shared__ float sred[32][KH];

    // ================= phase 1 =================
    if (tid < 3 * 16 * KH) {
        int j   = tid & 7;
        int d   = (tid >> 3) & 15;
        int dim = tid >> 7;
        int fk  = f * Kc + kh * KH + j;
        float coord = -1.0f + 2.0f * (float)d / 15.0f;
        float m, ls;
        if (dim == 0)      { m = lat_mean[fk]; ls = lat_logstd[fk]; }
        else if (dim == 1) { m = lon_mean[fk]; ls = lon_logstd[fk]; }
        else               { m = lev_mean[fk]; ls = lev_logstd[fk]; }
        float z = (coord - m) * expf(-ls);
        float g = expf(-0.5f * z * z);
        if (dim == 0)      sklat[d][j] = g;
        else if (dim == 1) sklon[d][j] = g;
        else               sklev[d][j] = g;
    }
    if (tid >= 512 && tid < 512 + KH) {
        int j = tid - 512;
        int fk = f * Kc + kh * KH + j;
        float tau = expf(time_logtau[fk]) + 1e-4f;
        float r = expf(-1.0f / tau);       // ktime[t] = r^t
        srate[j] = r;
        sr2[j] = r * r;
    }
    if (tid >= 768) {
        int i = tid - 768;
        float s = 0.f;
        #pragma unroll
        for (int bb = 0; bb < Bc; bb++) s += darea[bb * 256 + i];
        sdamean[i] = s * (1.f / 16.f);
        sda[i] = darea[b * 256 + i];
    }
    if (tid >= 704 && tid < 704 + Pc) {
        int i = tid - 704;
        float s = 0.f;
        #pragma unroll
        for (int bb = 0; bb < Bc; bb++) s += dlev[bb * Pc + i];
        sdlmean[i] = s * (1.f / 16.f);
        sdl[i] = dlev[b * Pc + i];
    }
    if (tid >= 736 && tid < 736 + Tc) {
        int i = tid - 736;
        float s = 0.f;
        #pragma unroll
        for (int bb = 0; bb < Bc; bb++) s += dtime[bb * Tc + i];
        sdtm[i] = s * (1.f / 16.f);
        sdt[i] = dtime[b * Tc + i];
    }
    __syncthreads();

    // ================= phase 2: tables + normalization integral =================
    {
        // fused (dt * darea) pair table: tid -> (y,x,i)
        int i  = tid & 3;
        int yx = tid >> 2;
        float da = sda[yx];
        sdtda[tid] = pk2(sdt[2 * i] * da, sdt[2 * i + 1] * da);
    }
    if (tid < Yc * KH) {               // duplicated klat pairs
        int j = tid & 7, y = tid >> 3;
        float v = sklat[y][j];
        sklat2[y][j] = pk2(v, v);
    }
    if (tid >= 256 && tid < 256 + KH) {
        int j = tid - 256;
        float v = sr2[j];
        ss2[j] = pk2(v, v);
    }
    {
        float c[KH];
        #pragma unroll
        for (int j = 0; j < KH; j++) c[j] = 0.f;
        if (tid < 256) {
            int yi = tid >> 4, xi = tid & 15;
            float dm = sdamean[tid];
            #pragma unroll
            for (int j = 0; j < KH; j++) c[j] = dm * sklat[yi][j] * sklon[xi][j];
        }
        if (warp < 8) {
            #pragma unroll
            for (int j = 0; j < KH; j++) {
                float v = c[j];
                #pragma unroll
                for (int o = 16; o > 0; o >>= 1) v += __shfl_xor_sync(0xFFFFFFFFu, v, o);
                if (lane == 0) sred[warp][j] = v;
            }
        }
        __syncthreads();
        if (tid < KH) {
            float Syx = 0.f;
            #pragma unroll
            for (int w = 0; w < 8; w++) Syx += sred[w][tid];
            float Sp = 0.f;
            #pragma unroll
            for (int pp = 0; pp < Pc; pp++) Sp = fmaf(sklev[pp][tid], sdlmean[pp], Sp);
            float r = srate[tid];
            float St = sdtm[Tc - 1];
            #pragma unroll
            for (int t = Tc - 2; t >= 0; t--) St = fmaf(St, r, sdtm[t]);
            swinv[tid] = 1.0f / (Syx * Sp * St + 1e-4f);
        }
        __syncthreads();   // tables + swinv visible; sred free for reuse
    }

    // ================= main contraction =================
    int p  = tid & 15;
    int x  = (tid >> 4) & 15;
    int yh = tid >> 8;                     // 0..3
    int y0 = yh * 4;

    const ulonglong2* src = (const ulonglong2*)(field
        + (size_t)(b * Fc + f) * (Yc * Xc * Pc * Tc)
        + (y0 * Xc * Pc + x * Pc + p) * Tc);
    // y-stride = 2048 floats = 512 ulonglong2

    u64 acc2[KH];
    #pragma unroll
    for (int k = 0; k < KH; k++) acc2[k] = pk2(0.f, 0.f);

    // pipeline: rows 0,1 preloaded; row yy+2 prefetched inside the loop
    ulonglong2 va[2][2];
    va[0][0] = src[0];    va[0][1] = src[1];
    va[1][0] = src[512];  va[1][1] = src[513];

    #pragma unroll
    for (int yy = 0; yy < 4; yy++) {
        ulonglong2 a0 = va[yy & 1][0], a1 = va[yy & 1][1];
        if (yy < 2) {
            va[yy & 1][0] = src[(yy + 2) * 512];
            va[yy & 1][1] = src[(yy + 2) * 512 + 1];
        }
        int y = y0 + yy;
        const u64* dd = &sdtda[((y << 4) | x) << 2];
        u64 q0 = mul2_(a0.x, dd[0]);
        u64 q1 = mul2_(a0.y, dd[1]);
        u64 q2 = mul2_(a1.x, dd[2]);
        u64 q3 = mul2_(a1.y, dd[3]);
        const u64* kl = &sklat2[y][0];
        #pragma unroll
        for (int k = 0; k < KH; k++) {
            u64 s2k = ss2[k];                  // uniform LDS.64 broadcast
            u64 d = fma2_(q3, s2k, q2);        // Horner in r^2, lanes (E,O)
            d = fma2_(d, s2k, q1);
            d = fma2_(d, s2k, q0);
            acc2[k] = fma2_(kl[k], d, acc2[k]); // klat[y]-pair * d, accumulate
        }
    }

    // deferred odd-lane correction + (x,p)-dependent factors, once per k
    float dlp = sdl[p];
    float av[KH];
    #pragma unroll
    for (int k = 0; k < KH; k++) {
        float E, O;
        unpk2(acc2[k], E, O);
        float dot = fmaf(srate[k], O, E);
        av[k] = dot * (sklon[x][k] * sklev[p][k] * dlp);
    }

    // ---- deterministic block reduction: shfl + fixed-order shared sum ----
    #pragma unroll
    for (int j = 0; j < KH; j++) {
        float v = av[j];
        #pragma unroll
        for (int o = 16; o > 0; o >>= 1) v += __shfl_xor_sync(0xFFFFFFFFu, v, o);
        if (lane == 0) sred[warp][j] = v;
    }
    __syncthreads();
    if (tid < KH) {
        float s = 0.f;
        #pragma unroll
        for (int w = 0; w < 32; w++) s += sred[w][tid];
        out[b * (Fc * Kc) + f * Kc + kh * KH + tid] = s * swinv[tid];
    }
}

extern "C" void kernel_launch(void* const* d_in, const int* in_sizes, int n_in,
                              void* d_out, int out_size)
{
    pkl_fused<<<Bc * Fc * 2, NT>>>(
        (const float*)d_in[0], (const float*)d_in[1],
        (const float*)d_in[2], (const float*)d_in[3],
        (const float*)d_in[4], (const float*)d_in[5],
        (const float*)d_in[6], (const float*)d_in[7],
        (const float*)d_in[8], (const float*)d_in[9],
        (const float*)d_in[10], (float*)d_out);
}